// round 14
// baseline (speedup 1.0000x reference)
#include <cuda_runtime.h>
#include <cuda_bf16.h>
#include <cstdint>
#include <math_constants.h>

#define HEADS 8
#define HD 32
#define NTOK 49
#define DIM 256
#define BATCH 2048
#define NWIN 64

// scratch (allocation-free rule: device globals)
__device__ float g_qkv[(size_t)BATCH * NTOK * 3 * DIM];      // [B, N, 768]
__device__ float g_ao[(size_t)BATCH * NTOK * DIM];           // attention out (tf32-rounded)
__device__ float g_wqt[3 * DIM * DIM];                       // tf32(qkv_w)^T [768][256]
__device__ float g_wpt[DIM * DIM];                           // tf32(proj_w)^T [256][256]
__device__ float g_comb[(size_t)NWIN * HEADS * NTOK * NTOK]; // [w][h][i][j]

__device__ __forceinline__ uint32_t f2tf32(float x) {
    uint32_t u;
    asm("cvt.rna.tf32.f32 %0, %1;" : "=r"(u) : "f"(x));
    return u;
}

__device__ __forceinline__ void mma_tf32(float* c, const uint32_t* a, const uint32_t* b) {
    asm volatile(
        "mma.sync.aligned.m16n8k8.row.col.f32.tf32.tf32.f32 "
        "{%0,%1,%2,%3}, {%4,%5,%6,%7}, {%8,%9}, {%0,%1,%2,%3};"
        : "+f"(c[0]), "+f"(c[1]), "+f"(c[2]), "+f"(c[3])
        : "r"(a[0]), "r"(a[1]), "r"(a[2]), "r"(a[3]), "r"(b[0]), "r"(b[1]));
}

__device__ __forceinline__ void mma_bf16(float* c, const uint32_t* a, const uint32_t* b) {
    asm volatile(
        "mma.sync.aligned.m16n8k16.row.col.f32.bf16.bf16.f32 "
        "{%0,%1,%2,%3}, {%4,%5,%6,%7}, {%8,%9}, {%0,%1,%2,%3};"
        : "+f"(c[0]), "+f"(c[1]), "+f"(c[2]), "+f"(c[3])
        : "r"(a[0]), "r"(a[1]), "r"(a[2]), "r"(a[3]), "r"(b[0]), "r"(b[1]));
}

__device__ __forceinline__ void ldsm_x4(uint32_t& r0, uint32_t& r1,
                                        uint32_t& r2, uint32_t& r3, uint32_t addr) {
    asm volatile("ldmatrix.sync.aligned.m8n8.x4.shared.b16 {%0,%1,%2,%3}, [%4];"
                 : "=r"(r0), "=r"(r1), "=r"(r2), "=r"(r3) : "r"(addr));
}

__device__ __forceinline__ void split_pack_bf16(float x, float y,
                                                uint32_t& hi, uint32_t& lo) {
    __nv_bfloat16 hx = __float2bfloat16(x);
    __nv_bfloat16 hy = __float2bfloat16(y);
    __nv_bfloat16 lx = __float2bfloat16(x - __bfloat162float(hx));
    __nv_bfloat16 ly = __float2bfloat16(y - __bfloat162float(hy));
    __nv_bfloat162 h; h.x = hx; h.y = hy;
    __nv_bfloat162 l; l.x = lx; l.y = ly;
    hi = *(uint32_t*)&h;
    lo = *(uint32_t*)&l;
}

__device__ __forceinline__ void cp16(uint32_t smem_dst, const void* gptr) {
    asm volatile("cp.async.cg.shared.global [%0], [%1], 16;\n"
                 :: "r"(smem_dst), "l"(gptr));
}

// ---------------------------------------------------------------------------
// prep: W[K][N] f32 -> Wt[N][K] tf32-rounded f32 (transpose)
// ---------------------------------------------------------------------------
__global__ __launch_bounds__(256) void transpose_tf32_kernel(
    const float* __restrict__ W, float* __restrict__ Wt, int K, int N)
{
    __shared__ float t[32][33];
    const int n0 = blockIdx.x * 32;
    const int k0 = blockIdx.y * 32;
    const int tx = threadIdx.x & 31;
    const int ty = threadIdx.x >> 5;
    #pragma unroll
    for (int i = 0; i < 4; i++) {
        const int k = ty + i * 8;
        t[k][tx] = W[(size_t)(k0 + k) * N + n0 + tx];
    }
    __syncthreads();
    #pragma unroll
    for (int i = 0; i < 4; i++) {
        const int r = ty + i * 8;
        Wt[(size_t)(n0 + r) * K + k0 + tx] = __uint_as_float(f2tf32(t[tx][r]));
    }
}

// ---------------------------------------------------------------------------
// TF32 mma.sync GEMM with ldmatrix frag loads, 3-stage cp.async pipeline.
// C[M,N] = A[M,K] @ Bt[N,K]^T + bias. BM=128, BN=128, BK=32, 128 threads
// (4 warps 2x2), warp tile 64x64. Both smem tiles [row][32k] stride 36.
// smem: 3 stages x 2 x 128 x 36 floats = 110592 B -> 2 CTAs/SM.
// ---------------------------------------------------------------------------
#define GEMM_STAGE_FLOATS (2 * 128 * 36)
#define GEMM_STAGES 3
#define GEMM_SMEM_BYTES (GEMM_STAGES * GEMM_STAGE_FLOATS * 4)

template<bool CVT_A>
__global__ __launch_bounds__(128) void gemm_tf32_lds(
    const float* __restrict__ A, const float* __restrict__ Bt,
    const float* __restrict__ bias, float* __restrict__ C,
    int M, int N, int K)
{
    constexpr int STR = 36;

    extern __shared__ float sm[];

    const int tid = threadIdx.x;
    const int wid = tid >> 5;
    const int lane = tid & 31;
    const int lr = lane >> 2;
    const int lc = lane & 3;
    const int wm = wid & 1;     // 2 m-tiles of 64
    const int wn = wid >> 1;    // 2 n-tiles of 64

    const int bm = blockIdx.y * 128;
    const int bn = blockIdx.x * 128;

    const uint32_t smem_base = (uint32_t)__cvta_generic_to_shared(sm);

    // ldmatrix per-thread addressing: lanes 0-7/8-15 -> rows, 16-31 -> col-block 4
    const int lrow = lane & 15;
    const int lcol4 = (lane >> 4) * 4;

    // issue one K-tile (128x32 A rows, 128x32 Bt rows) into stage s
    auto issue = [&](int k0, int s) {
        const uint32_t as_base = smem_base + (uint32_t)(s * GEMM_STAGE_FLOATS) * 4;
        const uint32_t bs_base = as_base + 128 * STR * 4;
        #pragma unroll
        for (int i = 0; i < 8; i++) {
            const int idx = tid + 128 * i;
            const int r = idx >> 3, c4 = idx & 7;
            cp16(as_base + (r * STR + c4 * 4) * 4,
                 A + (size_t)(bm + r) * K + k0 + c4 * 4);
        }
        #pragma unroll
        for (int i = 0; i < 8; i++) {
            const int idx = tid + 128 * i;
            const int r = idx >> 3, c4 = idx & 7;
            cp16(bs_base + (r * STR + c4 * 4) * 4,
                 Bt + (size_t)(bn + r) * K + k0 + c4 * 4);
        }
        asm volatile("cp.async.commit_group;\n" ::);
    };

    float acc[4][8][4] = {};   // [mi][ni][frag]

    const int niter = K / 32;   // 8
    issue(0, 0);
    issue(32, 1);

    for (int it = 0; it < niter; it++) {
        if (it < niter - 1)
            asm volatile("cp.async.wait_group 1;\n" ::);
        else
            asm volatile("cp.async.wait_group 0;\n" ::);
        __syncthreads();

        const int s = it % GEMM_STAGES;
        const uint32_t as_base = smem_base + (uint32_t)(s * GEMM_STAGE_FLOATS) * 4;
        const uint32_t bs_base = as_base + 128 * STR * 4;

        #pragma unroll
        for (int ks = 0; ks < 4; ks++) {
            const int k = ks * 8;
            uint32_t afr[4][4];
            #pragma unroll
            for (int mi = 0; mi < 4; mi++) {
                const int r0 = wm * 64 + mi * 16;
                const uint32_t addr =
                    as_base + (uint32_t)((r0 + lrow) * STR + k + lcol4) * 4;
                ldsm_x4(afr[mi][0], afr[mi][1], afr[mi][2], afr[mi][3], addr);
            }
            if (CVT_A) {
                #pragma unroll
                for (int mi = 0; mi < 4; mi++)
                    #pragma unroll
                    for (int q = 0; q < 4; q++)
                        afr[mi][q] = f2tf32(__uint_as_float(afr[mi][q]));
            }
            uint32_t bfr[8][2];
            #pragma unroll
            for (int p = 0; p < 4; p++) {           // pair of n-tiles
                const int n0 = wn * 64 + p * 16;
                const uint32_t addr =
                    bs_base + (uint32_t)((n0 + lrow) * STR + k + lcol4) * 4;
                uint32_t q0, q1, q2, q3;
                ldsm_x4(q0, q1, q2, q3, addr);
                bfr[2 * p][0] = q0;  bfr[2 * p][1] = q2;
                bfr[2 * p + 1][0] = q1;  bfr[2 * p + 1][1] = q3;
            }
            #pragma unroll
            for (int mi = 0; mi < 4; mi++)
                #pragma unroll
                for (int ni = 0; ni < 8; ni++)
                    mma_tf32(acc[mi][ni], afr[mi], bfr[ni]);
        }

        if (it + 2 < niter) issue((it + 2) * 32, (it + 2) % GEMM_STAGES);
    }

    // epilogue
    #pragma unroll
    for (int mi = 0; mi < 4; mi++) {
        #pragma unroll
        for (int ni = 0; ni < 8; ni++) {
            const int r0 = bm + wm * 64 + mi * 16 + lr;
            const int c0 = bn + wn * 64 + ni * 8 + lc * 2;
            float2 b01 = *(const float2*)(bias + c0);
            float2 v0 = make_float2(acc[mi][ni][0] + b01.x, acc[mi][ni][1] + b01.y);
            float2 v1 = make_float2(acc[mi][ni][2] + b01.x, acc[mi][ni][3] + b01.y);
            *(float2*)(C + (size_t)r0 * N + c0) = v0;
            *(float2*)(C + (size_t)(r0 + 8) * N + c0) = v1;
        }
    }
}

// ---------------------------------------------------------------------------
// comb[w][h][i][j] = mask[w][i][j] + bias_table[rel_index[i*49+j]][h]
// ---------------------------------------------------------------------------
__global__ __launch_bounds__(256) void comb_kernel(
    const float* __restrict__ mask, const float* __restrict__ bias_table,
    const int* __restrict__ rel_index, float* __restrict__ comb)
{
    const int total = NWIN * HEADS * NTOK * NTOK;
    int idx = blockIdx.x * 256 + threadIdx.x;
    if (idx < total) {
        const int ij = idx % (NTOK * NTOK);
        const int wh = idx / (NTOK * NTOK);
        const int h = wh & (HEADS - 1);
        const int w = wh >> 3;
        comb[idx] = mask[w * NTOK * NTOK + ij] + bias_table[rel_index[ij] * HEADS + h];
    }
}

// ---------------------------------------------------------------------------
// Register-resident-softmax bf16 attention (round-8 known good).
// ---------------------------------------------------------------------------
__global__ __launch_bounds__(128) void attn_reg_kernel(
    const float* __restrict__ qkv,       // [B, N, 768]
    const float* __restrict__ comb,      // [64][8][49][49]
    float* __restrict__ out)             // [B, N, 256] (tf32-rounded)
{
    __shared__ __align__(16) uint32_t sw[7104];
    uint32_t* Qh  = sw;            // 64 x 20
    uint32_t* Ql  = sw + 1280;
    uint32_t* Kh  = sw + 2560;     // 56 x 20
    uint32_t* Kl  = sw + 3680;
    uint32_t* Vth = sw + 4800;     // 32 x 36 (V transposed [d][j])
    uint32_t* Vtl = sw + 5952;

    const int b = blockIdx.x;
    const int h = blockIdx.y;
    const int tid = threadIdx.x;
    const int wid = tid >> 5;
    const int lane = tid & 31;
    const int lr = lane >> 2;
    const int lc = lane & 3;

    const float scale = 0.17677669529663687f;
    const float* base = qkv + (size_t)b * NTOK * 3 * DIM + h * HD;

    {
        __nv_bfloat16* vhH = (__nv_bfloat16*)Vth;
        __nv_bfloat16* vlH = (__nv_bfloat16*)Vtl;
        for (int e = tid; e < HD * 15; e += 128) {
            const int d = e / 15;
            const int j = NTOK + (e % 15);
            vhH[d * 72 + j] = __float2bfloat16(0.f);
            vlH[d * 72 + j] = __float2bfloat16(0.f);
        }
        for (int pe = tid; pe < NTOK * (HD / 2); pe += 128) {
            const int n = pe >> 4;
            const int dp = pe & 15;
            const int d = dp * 2;
            const float* row = base + (size_t)n * (3 * DIM) + d;
            float2 q2 = *(const float2*)(row);
            float2 k2 = *(const float2*)(row + DIM);
            float2 v2 = *(const float2*)(row + 2 * DIM);
            q2.x *= scale; q2.y *= scale;

            uint32_t hi, lo;
            split_pack_bf16(q2.x, q2.y, hi, lo);
            Qh[n * 20 + dp] = hi;
            Ql[n * 20 + dp] = lo;
            split_pack_bf16(k2.x, k2.y, hi, lo);
            Kh[n * 20 + dp] = hi;
            Kl[n * 20 + dp] = lo;

            __nv_bfloat16 vh0 = __float2bfloat16(v2.x);
            __nv_bfloat16 vh1 = __float2bfloat16(v2.y);
            __nv_bfloat16 vl0 = __float2bfloat16(v2.x - __bfloat162float(vh0));
            __nv_bfloat16 vl1 = __float2bfloat16(v2.y - __bfloat162float(vh1));
            vhH[d * 72 + n] = vh0;
            vhH[(d + 1) * 72 + n] = vh1;
            vlH[d * 72 + n] = vl0;
            vlH[(d + 1) * 72 + n] = vl1;
        }
    }
    __syncthreads();

    const int mr = wid * 16;

    float sacc[7][4] = {};
    #pragma unroll
    for (int kt = 0; kt < 2; kt++) {
        const int kw = kt * 8;
        uint32_t ah[4], al[4];
        ah[0] = Qh[(mr + lr) * 20 + kw + lc];
        ah[1] = Qh[(mr + 8 + lr) * 20 + kw + lc];
        ah[2] = Qh[(mr + lr) * 20 + kw + 4 + lc];
        ah[3] = Qh[(mr + 8 + lr) * 20 + kw + 4 + lc];
        al[0] = Ql[(mr + lr) * 20 + kw + lc];
        al[1] = Ql[(mr + 8 + lr) * 20 + kw + lc];
        al[2] = Ql[(mr + lr) * 20 + kw + 4 + lc];
        al[3] = Ql[(mr + 8 + lr) * 20 + kw + 4 + lc];

        #pragma unroll
        for (int nt = 0; nt < 7; nt++) {
            const int n0 = nt * 8;
            uint32_t bh[2], bl[2];
            bh[0] = Kh[(n0 + lr) * 20 + kw + lc];
            bh[1] = Kh[(n0 + lr) * 20 + kw + 4 + lc];
            bl[0] = Kl[(n0 + lr) * 20 + kw + lc];
            bl[1] = Kl[(n0 + lr) * 20 + kw + 4 + lc];
            mma_bf16(sacc[nt], ah, bh);
            mma_bf16(sacc[nt], al, bh);
            mma_bf16(sacc[nt], ah, bl);
        }
    }

    {
        const float* cb = comb + ((size_t)((b & (NWIN - 1)) * HEADS + h)) * (NTOK * NTOK);
        const int rA = mr + lr;
        const int rB = mr + 8 + lr;
        const bool okA = rA < NTOK;
        const bool okB = rB < NTOK;
        float mA = -CUDART_INF_F, mB = -CUDART_INF_F;

        #pragma unroll
        for (int nt = 0; nt < 7; nt++) {
            const int c0 = nt * 8 + 2 * lc;
            const bool ok0 = c0 < NTOK;
            const bool ok1 = (c0 + 1) < NTOK;
            float v0A = (okA && ok0) ? sacc[nt][0] + __ldg(cb + rA * NTOK + c0)     : -CUDART_INF_F;
            float v1A = (okA && ok1) ? sacc[nt][1] + __ldg(cb + rA * NTOK + c0 + 1) : -CUDART_INF_F;
            float v0B = (okB && ok0) ? sacc[nt][2] + __ldg(cb + rB * NTOK + c0)     : -CUDART_INF_F;
            float v1B = (okB && ok1) ? sacc[nt][3] + __ldg(cb + rB * NTOK + c0 + 1) : -CUDART_INF_F;
            sacc[nt][0] = v0A; sacc[nt][1] = v1A;
            sacc[nt][2] = v0B; sacc[nt][3] = v1B;
            mA = fmaxf(mA, fmaxf(v0A, v1A));
            mB = fmaxf(mB, fmaxf(v0B, v1B));
        }
        mA = fmaxf(mA, __shfl_xor_sync(0xffffffffu, mA, 1));
        mA = fmaxf(mA, __shfl_xor_sync(0xffffffffu, mA, 2));
        mB = fmaxf(mB, __shfl_xor_sync(0xffffffffu, mB, 1));
        mB = fmaxf(mB, __shfl_xor_sync(0xffffffffu, mB, 2));

        float sA = 0.f, sB = 0.f;
        #pragma unroll
        for (int nt = 0; nt < 7; nt++) {
            float e0A = __expf(sacc[nt][0] - mA);
            float e1A = __expf(sacc[nt][1] - mA);
            float e0B = __expf(sacc[nt][2] - mB);
            float e1B = __expf(sacc[nt][3] - mB);
            sacc[nt][0] = e0A; sacc[nt][1] = e1A;
            sacc[nt][2] = e0B; sacc[nt][3] = e1B;
            sA += e0A + e1A;
            sB += e0B + e1B;
        }
        sA += __shfl_xor_sync(0xffffffffu, sA, 1);
        sA += __shfl_xor_sync(0xffffffffu, sA, 2);
        sB += __shfl_xor_sync(0xffffffffu, sB, 1);
        sB += __shfl_xor_sync(0xffffffffu, sB, 2);
        const float invA = 1.f / sA;
        const float invB = 1.f / sB;
        #pragma unroll
        for (int nt = 0; nt < 7; nt++) {
            sacc[nt][0] *= invA; sacc[nt][1] *= invA;
            sacc[nt][2] *= invB; sacc[nt][3] *= invB;
        }
    }

    {
        float oacc[4][4] = {};
        #pragma unroll
        for (int kt = 0; kt < 4; kt++) {
            const int kw = kt * 8;
            const int t0 = 2 * kt;
            const int t1 = 2 * kt + 1;
            uint32_t ah[4], al[4];
            split_pack_bf16(sacc[t0][0], sacc[t0][1], ah[0], al[0]);
            split_pack_bf16(sacc[t0][2], sacc[t0][3], ah[1], al[1]);
            if (t1 < 7) {
                split_pack_bf16(sacc[t1][0], sacc[t1][1], ah[2], al[2]);
                split_pack_bf16(sacc[t1][2], sacc[t1][3], ah[3], al[3]);
            } else {
                ah[2] = ah[3] = al[2] = al[3] = 0u;
            }

            #pragma unroll
            for (int nt = 0; nt < 4; nt++) {
                const int n0 = nt * 8;
                uint32_t bh[2], bl[2];
                bh[0] = Vth[(n0 + lr) * 36 + kw + lc];
                bh[1] = Vth[(n0 + lr) * 36 + kw + 4 + lc];
                bl[0] = Vtl[(n0 + lr) * 36 + kw + lc];
                bl[1] = Vtl[(n0 + lr) * 36 + kw + 4 + lc];
                mma_bf16(oacc[nt], ah, bh);
                mma_bf16(oacc[nt], al, bh);
                mma_bf16(oacc[nt], ah, bl);
            }
        }

        const int r0 = mr + lr;
        const int r1 = mr + 8 + lr;
        #pragma unroll
        for (int nt = 0; nt < 4; nt++) {
            const int c0 = h * HD + nt * 8 + lc * 2;
            if (r0 < NTOK) {
                float2 v = make_float2(__uint_as_float(f2tf32(oacc[nt][0])),
                                       __uint_as_float(f2tf32(oacc[nt][1])));
                *(float2*)(out + ((size_t)b * NTOK + r0) * DIM + c0) = v;
            }
            if (r1 < NTOK) {
                float2 v = make_float2(__uint_as_float(f2tf32(oacc[nt][2])),
                                       __uint_as_float(f2tf32(oacc[nt][3])));
                *(float2*)(out + ((size_t)b * NTOK + r1) * DIM + c0) = v;
            }
        }
    }
}

// ---------------------------------------------------------------------------
extern "C" void kernel_launch(void* const* d_in, const int* in_sizes, int n_in,
                              void* d_out, int out_size)
{
    const float* x          = (const float*)d_in[0];
    const float* mask       = (const float*)d_in[1];
    const float* qkv_w      = (const float*)d_in[2];
    const float* qkv_b      = (const float*)d_in[3];
    const float* proj_w     = (const float*)d_in[4];
    const float* proj_b     = (const float*)d_in[5];
    const float* bias_table = (const float*)d_in[6];
    const int*   rel_index  = (const int*)d_in[7];
    float* out = (float*)d_out;

    float *qkv_buf, *ao_buf, *wqt_buf, *wpt_buf, *comb_buf;
    cudaGetSymbolAddress((void**)&qkv_buf, g_qkv);
    cudaGetSymbolAddress((void**)&ao_buf, g_ao);
    cudaGetSymbolAddress((void**)&wqt_buf, g_wqt);
    cudaGetSymbolAddress((void**)&wpt_buf, g_wpt);
    cudaGetSymbolAddress((void**)&comb_buf, g_comb);

    static bool attr_set = false;
    if (!attr_set) {
        cudaFuncSetAttribute(gemm_tf32_lds<true>,
                             cudaFuncAttributeMaxDynamicSharedMemorySize,
                             GEMM_SMEM_BYTES);
        cudaFuncSetAttribute(gemm_tf32_lds<false>,
                             cudaFuncAttributeMaxDynamicSharedMemorySize,
                             GEMM_SMEM_BYTES);
        attr_set = true;
    }

    const int M = BATCH * NTOK;   // 100352 = 128 * 784

    // 0a) transpose + tf32-round weights
    {
        dim3 g1(3 * DIM / 32, DIM / 32);
        transpose_tf32_kernel<<<g1, 256>>>(qkv_w, wqt_buf, DIM, 3 * DIM);
        dim3 g2(DIM / 32, DIM / 32);
        transpose_tf32_kernel<<<g2, 256>>>(proj_w, wpt_buf, DIM, DIM);
    }
    // 0b) combined bias+mask table
    {
        const int total = NWIN * HEADS * NTOK * NTOK;
        comb_kernel<<<(total + 255) / 256, 256>>>(mask, bias_table, rel_index, comb_buf);
    }
    // 1) QKV GEMM: raw f32 x (cvt in frag path), Bt = wqt [768][256]
    {
        dim3 grid(3 * DIM / 128, M / 128);
        gemm_tf32_lds<true><<<grid, 128, GEMM_SMEM_BYTES>>>(x, wqt_buf, qkv_b, qkv_buf,
                                                            M, 3 * DIM, DIM);
    }
    // 2) register-softmax attention (emits tf32-rounded output)
    {
        dim3 grid(BATCH, HEADS);
        attn_reg_kernel<<<grid, 128>>>(qkv_buf, comb_buf, ao_buf);
    }
    // 3) Proj GEMM: A already tf32-rounded, Bt = wpt [256][256]
    {
        dim3 grid(DIM / 128, M / 128);
        gemm_tf32_lds<false><<<grid, 128, GEMM_SMEM_BYTES>>>(ao_buf, wpt_buf, proj_b, out,
                                                             M, DIM, DIM);
    }
}

// round 15
// speedup vs baseline: 1.3088x; 1.3088x over previous
#include <cuda_runtime.h>
#include <cuda_bf16.h>
#include <cuda_fp16.h>
#include <cstdint>
#include <math_constants.h>

#define HEADS 8
#define HD 32
#define NTOK 49
#define DIM 256
#define BATCH 2048
#define NWIN 64

// scratch (allocation-free rule: device globals)
__device__ uint32_t g_xp[(size_t)BATCH * NTOK * DIM / 2];     // x packed half2 [M][128]
__device__ float    g_qkv[(size_t)BATCH * NTOK * 3 * DIM];    // [B, N, 768] f32
__device__ uint32_t g_aop[(size_t)BATCH * NTOK * DIM / 2];    // attn out packed half2 [M][128]
__device__ uint32_t g_wqp[(DIM / 2) * 3 * DIM];               // qkv_w packed [128][768]
__device__ uint32_t g_wpp[(DIM / 2) * DIM];                   // proj_w packed [128][256]
__device__ float    g_comb[(size_t)NWIN * HEADS * NTOK * NTOK];

__device__ __forceinline__ void mma_f16(float* c, const uint32_t* a, const uint32_t* b) {
    asm volatile(
        "mma.sync.aligned.m16n8k16.row.col.f32.f16.f16.f32 "
        "{%0,%1,%2,%3}, {%4,%5,%6,%7}, {%8,%9}, {%0,%1,%2,%3};"
        : "+f"(c[0]), "+f"(c[1]), "+f"(c[2]), "+f"(c[3])
        : "r"(a[0]), "r"(a[1]), "r"(a[2]), "r"(a[3]), "r"(b[0]), "r"(b[1]));
}

__device__ __forceinline__ void mma_bf16(float* c, const uint32_t* a, const uint32_t* b) {
    asm volatile(
        "mma.sync.aligned.m16n8k16.row.col.f32.bf16.bf16.f32 "
        "{%0,%1,%2,%3}, {%4,%5,%6,%7}, {%8,%9}, {%0,%1,%2,%3};"
        : "+f"(c[0]), "+f"(c[1]), "+f"(c[2]), "+f"(c[3])
        : "r"(a[0]), "r"(a[1]), "r"(a[2]), "r"(a[3]), "r"(b[0]), "r"(b[1]));
}

__device__ __forceinline__ void split_pack_bf16(float x, float y,
                                                uint32_t& hi, uint32_t& lo) {
    __nv_bfloat16 hx = __float2bfloat16(x);
    __nv_bfloat16 hy = __float2bfloat16(y);
    __nv_bfloat16 lx = __float2bfloat16(x - __bfloat162float(hx));
    __nv_bfloat16 ly = __float2bfloat16(y - __bfloat162float(hy));
    __nv_bfloat162 h; h.x = hx; h.y = hy;
    __nv_bfloat162 l; l.x = lx; l.y = ly;
    hi = *(uint32_t*)&h;
    lo = *(uint32_t*)&l;
}

__device__ __forceinline__ void cp16(uint32_t smem_dst, const void* gptr) {
    asm volatile("cp.async.cg.shared.global [%0], [%1], 16;\n"
                 :: "r"(smem_dst), "l"(gptr));
}

// ---------------------------------------------------------------------------
// prep: pack f32 pairs -> half2 words
// ---------------------------------------------------------------------------
__global__ __launch_bounds__(256) void pack_fp16_kernel(
    const float2* __restrict__ src, uint32_t* __restrict__ dst, int n)
{
    for (int i = blockIdx.x * 256 + threadIdx.x; i < n; i += gridDim.x * 256) {
        float2 v = src[i];
        __half2 h = __floats2half2_rn(v.x, v.y);
        dst[i] = *(uint32_t*)&h;
    }
}

// W[K][N] f32 -> Wp[K/2][N] uint32: word(kk,n) = {h(W[2kk][n]), h(W[2kk+1][n])}
__global__ __launch_bounds__(256) void pack_w_kernel(
    const float* __restrict__ W, uint32_t* __restrict__ Wp, int K, int N)
{
    const int total = (K / 2) * N;
    for (int i = blockIdx.x * 256 + threadIdx.x; i < total; i += gridDim.x * 256) {
        const int kk = i / N;
        const int n = i - kk * N;
        __half2 h = __floats2half2_rn(W[(size_t)(2 * kk) * N + n],
                                      W[(size_t)(2 * kk + 1) * N + n]);
        Wp[i] = *(uint32_t*)&h;
    }
}

// ---------------------------------------------------------------------------
// FP16 mma.sync GEMM, 3-stage cp.async pipeline, one barrier per K-iter.
// C[M,N] = A[M,K] @ B[K,N] + bias, A/B packed half2 along K.
// BM=128, BN=128, BK=32, 128 threads (4 warps 2x2), warp tile 64x64.
// smem words/stage: A 128*20 + B 16*136 = 4736 -> 3 stages = 56832 B.
// ---------------------------------------------------------------------------
#define GEMM_STAGE_WORDS (128 * 20 + 16 * 136)
#define GEMM_STAGES 3
#define GEMM_SMEM_BYTES (GEMM_STAGES * GEMM_STAGE_WORDS * 4)

__global__ __launch_bounds__(128) void gemm_fp16(
    const uint32_t* __restrict__ Ap,   // [M][K/2]
    const uint32_t* __restrict__ Bp,   // [K/2][N]
    const float* __restrict__ bias, float* __restrict__ C,
    int M, int N, int K)
{
    constexpr int ASTR = 20, BSTR = 136;
    const int K2 = K / 2;

    extern __shared__ uint32_t sm[];

    const int tid = threadIdx.x;
    const int wid = tid >> 5;
    const int lane = tid & 31;
    const int lr = lane >> 2;
    const int lc = lane & 3;
    const int wm = wid & 1;     // 2 m-tiles of 64
    const int wn = wid >> 1;    // 2 n-tiles of 64

    const int bm = blockIdx.y * 128;
    const int bn = blockIdx.x * 128;

    const uint32_t smem_base = (uint32_t)__cvta_generic_to_shared(sm);

    // one K-tile = 32 k = 16 packed rows. A: 128x16 words, B: 16x128 words.
    auto issue = [&](int k0, int s) {
        const int k20 = k0 >> 1;
        const uint32_t as_base = smem_base + (uint32_t)(s * GEMM_STAGE_WORDS) * 4;
        const uint32_t bs_base = as_base + 128 * ASTR * 4;
        #pragma unroll
        for (int i = 0; i < 4; i++) {
            const int idx = tid + 128 * i;
            const int r = idx >> 2, q = idx & 3;
            cp16(as_base + (r * ASTR + q * 4) * 4,
                 Ap + (size_t)(bm + r) * K2 + k20 + q * 4);
        }
        #pragma unroll
        for (int i = 0; i < 4; i++) {
            const int idx = tid + 128 * i;
            const int r = idx >> 5, c = idx & 31;
            cp16(bs_base + (r * BSTR + c * 4) * 4,
                 Bp + (size_t)(k20 + r) * N + bn + c * 4);
        }
        asm volatile("cp.async.commit_group;\n" ::);
    };

    float acc[4][8][4] = {};   // [mi][ni][frag]

    const int niter = K / 32;   // 8
    issue(0, 0);
    issue(32, 1);

    for (int it = 0; it < niter; it++) {
        if (it < niter - 1)
            asm volatile("cp.async.wait_group 1;\n" ::);
        else
            asm volatile("cp.async.wait_group 0;\n" ::);
        __syncthreads();

        const int s = it % GEMM_STAGES;
        const uint32_t* As = sm + s * GEMM_STAGE_WORDS;
        const uint32_t* Bs = As + 128 * ASTR;

        #pragma unroll
        for (int ks = 0; ks < 2; ks++) {            // 2 x k16 per tile
            const int k2b = ks * 8;                 // packed-word base
            uint32_t afr[4][4];
            #pragma unroll
            for (int mi = 0; mi < 4; mi++) {
                const int r = wm * 64 + mi * 16;
                afr[mi][0] = As[(r + lr) * ASTR + k2b + lc];
                afr[mi][1] = As[(r + 8 + lr) * ASTR + k2b + lc];
                afr[mi][2] = As[(r + lr) * ASTR + k2b + 4 + lc];
                afr[mi][3] = As[(r + 8 + lr) * ASTR + k2b + 4 + lc];
            }
            uint32_t bfr[8][2];
            #pragma unroll
            for (int ni = 0; ni < 8; ni++) {
                const int c = wn * 64 + ni * 8 + lr;
                bfr[ni][0] = Bs[(k2b + lc) * BSTR + c];
                bfr[ni][1] = Bs[(k2b + 4 + lc) * BSTR + c];
            }
            #pragma unroll
            for (int mi = 0; mi < 4; mi++)
                #pragma unroll
                for (int ni = 0; ni < 8; ni++)
                    mma_f16(acc[mi][ni], afr[mi], bfr[ni]);
        }

        if (it + 2 < niter) issue((it + 2) * 32, (it + 2) % GEMM_STAGES);
    }

    // epilogue
    #pragma unroll
    for (int mi = 0; mi < 4; mi++) {
        #pragma unroll
        for (int ni = 0; ni < 8; ni++) {
            const int r0 = bm + wm * 64 + mi * 16 + lr;
            const int c0 = bn + wn * 64 + ni * 8 + lc * 2;
            float2 b01 = *(const float2*)(bias + c0);
            float2 v0 = make_float2(acc[mi][ni][0] + b01.x, acc[mi][ni][1] + b01.y);
            float2 v1 = make_float2(acc[mi][ni][2] + b01.x, acc[mi][ni][3] + b01.y);
            *(float2*)(C + (size_t)r0 * N + c0) = v0;
            *(float2*)(C + (size_t)(r0 + 8) * N + c0) = v1;
        }
    }
}

// ---------------------------------------------------------------------------
// comb[w][h][i][j] = mask[w][i][j] + bias_table[rel_index[i*49+j]][h]
// ---------------------------------------------------------------------------
__global__ __launch_bounds__(256) void comb_kernel(
    const float* __restrict__ mask, const float* __restrict__ bias_table,
    const int* __restrict__ rel_index, float* __restrict__ comb)
{
    const int total = NWIN * HEADS * NTOK * NTOK;
    int idx = blockIdx.x * 256 + threadIdx.x;
    if (idx < total) {
        const int ij = idx % (NTOK * NTOK);
        const int wh = idx / (NTOK * NTOK);
        const int h = wh & (HEADS - 1);
        const int w = wh >> 3;
        comb[idx] = mask[w * NTOK * NTOK + ij] + bias_table[rel_index[ij] * HEADS + h];
    }
}

// ---------------------------------------------------------------------------
// Register-resident-softmax bf16 attention; emits packed half2 output.
// ---------------------------------------------------------------------------
__global__ __launch_bounds__(128) void attn_reg_kernel(
    const float* __restrict__ qkv,       // [B, N, 768]
    const float* __restrict__ comb,      // [64][8][49][49]
    uint32_t* __restrict__ outp)         // [M][128] packed half2
{
    __shared__ __align__(16) uint32_t sw[7104];
    uint32_t* Qh  = sw;            // 64 x 20
    uint32_t* Ql  = sw + 1280;
    uint32_t* Kh  = sw + 2560;     // 56 x 20
    uint32_t* Kl  = sw + 3680;
    uint32_t* Vth = sw + 4800;     // 32 x 36 (V transposed [d][j])
    uint32_t* Vtl = sw + 5952;

    const int b = blockIdx.x;
    const int h = blockIdx.y;
    const int tid = threadIdx.x;
    const int wid = tid >> 5;
    const int lane = tid & 31;
    const int lr = lane >> 2;
    const int lc = lane & 3;

    const float scale = 0.17677669529663687f;
    const float* base = qkv + (size_t)b * NTOK * 3 * DIM + h * HD;

    {
        __nv_bfloat16* vhH = (__nv_bfloat16*)Vth;
        __nv_bfloat16* vlH = (__nv_bfloat16*)Vtl;
        for (int e = tid; e < HD * 15; e += 128) {
            const int d = e / 15;
            const int j = NTOK + (e % 15);
            vhH[d * 72 + j] = __float2bfloat16(0.f);
            vlH[d * 72 + j] = __float2bfloat16(0.f);
        }
        for (int pe = tid; pe < NTOK * (HD / 2); pe += 128) {
            const int n = pe >> 4;
            const int dp = pe & 15;
            const int d = dp * 2;
            const float* row = base + (size_t)n * (3 * DIM) + d;
            float2 q2 = *(const float2*)(row);
            float2 k2 = *(const float2*)(row + DIM);
            float2 v2 = *(const float2*)(row + 2 * DIM);
            q2.x *= scale; q2.y *= scale;

            uint32_t hi, lo;
            split_pack_bf16(q2.x, q2.y, hi, lo);
            Qh[n * 20 + dp] = hi;
            Ql[n * 20 + dp] = lo;
            split_pack_bf16(k2.x, k2.y, hi, lo);
            Kh[n * 20 + dp] = hi;
            Kl[n * 20 + dp] = lo;

            __nv_bfloat16 vh0 = __float2bfloat16(v2.x);
            __nv_bfloat16 vh1 = __float2bfloat16(v2.y);
            __nv_bfloat16 vl0 = __float2bfloat16(v2.x - __bfloat162float(vh0));
            __nv_bfloat16 vl1 = __float2bfloat16(v2.y - __bfloat162float(vh1));
            vhH[d * 72 + n] = vh0;
            vhH[(d + 1) * 72 + n] = vh1;
            vlH[d * 72 + n] = vl0;
            vlH[(d + 1) * 72 + n] = vl1;
        }
    }
    __syncthreads();

    const int mr = wid * 16;

    float sacc[7][4] = {};
    #pragma unroll
    for (int kt = 0; kt < 2; kt++) {
        const int kw = kt * 8;
        uint32_t ah[4], al[4];
        ah[0] = Qh[(mr + lr) * 20 + kw + lc];
        ah[1] = Qh[(mr + 8 + lr) * 20 + kw + lc];
        ah[2] = Qh[(mr + lr) * 20 + kw + 4 + lc];
        ah[3] = Qh[(mr + 8 + lr) * 20 + kw + 4 + lc];
        al[0] = Ql[(mr + lr) * 20 + kw + lc];
        al[1] = Ql[(mr + 8 + lr) * 20 + kw + lc];
        al[2] = Ql[(mr + lr) * 20 + kw + 4 + lc];
        al[3] = Ql[(mr + 8 + lr) * 20 + kw + 4 + lc];

        #pragma unroll
        for (int nt = 0; nt < 7; nt++) {
            const int n0 = nt * 8;
            uint32_t bh[2], bl[2];
            bh[0] = Kh[(n0 + lr) * 20 + kw + lc];
            bh[1] = Kh[(n0 + lr) * 20 + kw + 4 + lc];
            bl[0] = Kl[(n0 + lr) * 20 + kw + lc];
            bl[1] = Kl[(n0 + lr) * 20 + kw + 4 + lc];
            mma_bf16(sacc[nt], ah, bh);
            mma_bf16(sacc[nt], al, bh);
            mma_bf16(sacc[nt], ah, bl);
        }
    }

    {
        const float* cb = comb + ((size_t)((b & (NWIN - 1)) * HEADS + h)) * (NTOK * NTOK);
        const int rA = mr + lr;
        const int rB = mr + 8 + lr;
        const bool okA = rA < NTOK;
        const bool okB = rB < NTOK;
        float mA = -CUDART_INF_F, mB = -CUDART_INF_F;

        #pragma unroll
        for (int nt = 0; nt < 7; nt++) {
            const int c0 = nt * 8 + 2 * lc;
            const bool ok0 = c0 < NTOK;
            const bool ok1 = (c0 + 1) < NTOK;
            float v0A = (okA && ok0) ? sacc[nt][0] + __ldg(cb + rA * NTOK + c0)     : -CUDART_INF_F;
            float v1A = (okA && ok1) ? sacc[nt][1] + __ldg(cb + rA * NTOK + c0 + 1) : -CUDART_INF_F;
            float v0B = (okB && ok0) ? sacc[nt][2] + __ldg(cb + rB * NTOK + c0)     : -CUDART_INF_F;
            float v1B = (okB && ok1) ? sacc[nt][3] + __ldg(cb + rB * NTOK + c0 + 1) : -CUDART_INF_F;
            sacc[nt][0] = v0A; sacc[nt][1] = v1A;
            sacc[nt][2] = v0B; sacc[nt][3] = v1B;
            mA = fmaxf(mA, fmaxf(v0A, v1A));
            mB = fmaxf(mB, fmaxf(v0B, v1B));
        }
        mA = fmaxf(mA, __shfl_xor_sync(0xffffffffu, mA, 1));
        mA = fmaxf(mA, __shfl_xor_sync(0xffffffffu, mA, 2));
        mB = fmaxf(mB, __shfl_xor_sync(0xffffffffu, mB, 1));
        mB = fmaxf(mB, __shfl_xor_sync(0xffffffffu, mB, 2));

        float sA = 0.f, sB = 0.f;
        #pragma unroll
        for (int nt = 0; nt < 7; nt++) {
            float e0A = __expf(sacc[nt][0] - mA);
            float e1A = __expf(sacc[nt][1] - mA);
            float e0B = __expf(sacc[nt][2] - mB);
            float e1B = __expf(sacc[nt][3] - mB);
            sacc[nt][0] = e0A; sacc[nt][1] = e1A;
            sacc[nt][2] = e0B; sacc[nt][3] = e1B;
            sA += e0A + e1A;
            sB += e0B + e1B;
        }
        sA += __shfl_xor_sync(0xffffffffu, sA, 1);
        sA += __shfl_xor_sync(0xffffffffu, sA, 2);
        sB += __shfl_xor_sync(0xffffffffu, sB, 1);
        sB += __shfl_xor_sync(0xffffffffu, sB, 2);
        const float invA = 1.f / sA;
        const float invB = 1.f / sB;
        #pragma unroll
        for (int nt = 0; nt < 7; nt++) {
            sacc[nt][0] *= invA; sacc[nt][1] *= invA;
            sacc[nt][2] *= invB; sacc[nt][3] *= invB;
        }
    }

    {
        float oacc[4][4] = {};
        #pragma unroll
        for (int kt = 0; kt < 4; kt++) {
            const int kw = kt * 8;
            const int t0 = 2 * kt;
            const int t1 = 2 * kt + 1;
            uint32_t ah[4], al[4];
            split_pack_bf16(sacc[t0][0], sacc[t0][1], ah[0], al[0]);
            split_pack_bf16(sacc[t0][2], sacc[t0][3], ah[1], al[1]);
            if (t1 < 7) {
                split_pack_bf16(sacc[t1][0], sacc[t1][1], ah[2], al[2]);
                split_pack_bf16(sacc[t1][2], sacc[t1][3], ah[3], al[3]);
            } else {
                ah[2] = ah[3] = al[2] = al[3] = 0u;
            }

            #pragma unroll
            for (int nt = 0; nt < 4; nt++) {
                const int n0 = nt * 8;
                uint32_t bh[2], bl[2];
                bh[0] = Vth[(n0 + lr) * 36 + kw + lc];
                bh[1] = Vth[(n0 + lr) * 36 + kw + 4 + lc];
                bl[0] = Vtl[(n0 + lr) * 36 + kw + lc];
                bl[1] = Vtl[(n0 + lr) * 36 + kw + 4 + lc];
                mma_bf16(oacc[nt], ah, bh);
                mma_bf16(oacc[nt], al, bh);
                mma_bf16(oacc[nt], ah, bl);
            }
        }

        const int r0 = mr + lr;
        const int r1 = mr + 8 + lr;
        #pragma unroll
        for (int nt = 0; nt < 4; nt++) {
            const int w0 = (h * HD + nt * 8 + lc * 2) >> 1;   // packed word index
            if (r0 < NTOK) {
                __half2 hv = __floats2half2_rn(oacc[nt][0], oacc[nt][1]);
                outp[((size_t)b * NTOK + r0) * (DIM / 2) + w0] = *(uint32_t*)&hv;
            }
            if (r1 < NTOK) {
                __half2 hv = __floats2half2_rn(oacc[nt][2], oacc[nt][3]);
                outp[((size_t)b * NTOK + r1) * (DIM / 2) + w0] = *(uint32_t*)&hv;
            }
        }
    }
}

// ---------------------------------------------------------------------------
extern "C" void kernel_launch(void* const* d_in, const int* in_sizes, int n_in,
                              void* d_out, int out_size)
{
    const float* x          = (const float*)d_in[0];
    const float* mask       = (const float*)d_in[1];
    const float* qkv_w      = (const float*)d_in[2];
    const float* qkv_b      = (const float*)d_in[3];
    const float* proj_w     = (const float*)d_in[4];
    const float* proj_b     = (const float*)d_in[5];
    const float* bias_table = (const float*)d_in[6];
    const int*   rel_index  = (const int*)d_in[7];
    float* out = (float*)d_out;

    uint32_t *xp_buf, *aop_buf, *wqp_buf, *wpp_buf;
    float *qkv_buf, *comb_buf;
    cudaGetSymbolAddress((void**)&xp_buf, g_xp);
    cudaGetSymbolAddress((void**)&qkv_buf, g_qkv);
    cudaGetSymbolAddress((void**)&aop_buf, g_aop);
    cudaGetSymbolAddress((void**)&wqp_buf, g_wqp);
    cudaGetSymbolAddress((void**)&wpp_buf, g_wpp);
    cudaGetSymbolAddress((void**)&comb_buf, g_comb);

    static bool attr_set = false;
    if (!attr_set) {
        cudaFuncSetAttribute(gemm_fp16,
                             cudaFuncAttributeMaxDynamicSharedMemorySize,
                             GEMM_SMEM_BYTES);
        attr_set = true;
    }

    const int M = BATCH * NTOK;   // 100352 = 128 * 784

    // 0a) pack x and weights to fp16 pairs
    pack_fp16_kernel<<<2048, 256>>>((const float2*)x, xp_buf, M * DIM / 2);
    pack_w_kernel<<<384, 256>>>(qkv_w, wqp_buf, DIM, 3 * DIM);
    pack_w_kernel<<<128, 256>>>(proj_w, wpp_buf, DIM, DIM);
    // 0b) combined bias+mask table
    {
        const int total = NWIN * HEADS * NTOK * NTOK;
        comb_kernel<<<(total + 255) / 256, 256>>>(mask, bias_table, rel_index, comb_buf);
    }
    // 1) QKV GEMM (fp16): [M,256] @ [256,768] + b -> f32
    {
        dim3 grid(3 * DIM / 128, M / 128);
        gemm_fp16<<<grid, 128, GEMM_SMEM_BYTES>>>(xp_buf, wqp_buf, qkv_b, qkv_buf,
                                                  M, 3 * DIM, DIM);
    }
    // 2) register-softmax attention -> packed half2
    {
        dim3 grid(BATCH, HEADS);
        attn_reg_kernel<<<grid, 128>>>(qkv_buf, comb_buf, aop_buf);
    }
    // 3) Proj GEMM (fp16): [M,256] @ [256,256] + b -> out f32
    {
        dim3 grid(DIM / 128, M / 128);
        gemm_fp16<<<grid, 128, GEMM_SMEM_BYTES>>>(aop_buf, wpp_buf, proj_b, out,
                                                  M, DIM, DIM);
    }
}

// round 16
// speedup vs baseline: 1.4981x; 1.1446x over previous
#include <cuda_runtime.h>
#include <cuda_fp16.h>
#include <cstdint>
#include <math_constants.h>

#define HEADS 8
#define HD 32
#define NTOK 49
#define DIM 256
#define BATCH 2048
#define NWIN 64

// scratch (allocation-free rule: device globals)
__device__ uint32_t g_xp[(size_t)BATCH * NTOK * DIM / 2];      // x packed half2 [M][128]
__device__ uint32_t g_qkvp[(size_t)BATCH * NTOK * 3 * DIM / 2];// qkv packed [M][384]
__device__ uint32_t g_aop[(size_t)BATCH * NTOK * DIM / 2];     // attn out packed [M][128]
__device__ uint32_t g_wqp[(DIM / 2) * 3 * DIM];                // qkv_w packed [128][768] (q-cols pre-scaled)
__device__ uint32_t g_wpp[(DIM / 2) * DIM];                    // proj_w packed [128][256]
__device__ float    g_qbs[3 * DIM];                            // scaled qkv bias
__device__ float    g_comb[(size_t)NWIN * HEADS * NTOK * NTOK];

#define QSCALE 0.17677669529663687f

__device__ __forceinline__ void mma_f16(float* c, const uint32_t* a, const uint32_t* b) {
    asm volatile(
        "mma.sync.aligned.m16n8k16.row.col.f32.f16.f16.f32 "
        "{%0,%1,%2,%3}, {%4,%5,%6,%7}, {%8,%9}, {%0,%1,%2,%3};"
        : "+f"(c[0]), "+f"(c[1]), "+f"(c[2]), "+f"(c[3])
        : "r"(a[0]), "r"(a[1]), "r"(a[2]), "r"(a[3]), "r"(b[0]), "r"(b[1]));
}

__device__ __forceinline__ void cp16(uint32_t smem_dst, const void* gptr) {
    asm volatile("cp.async.cg.shared.global [%0], [%1], 16;\n"
                 :: "r"(smem_dst), "l"(gptr));
}

// ---------------------------------------------------------------------------
// prep kernels
// ---------------------------------------------------------------------------
__global__ __launch_bounds__(256) void pack_fp16_kernel(
    const float2* __restrict__ src, uint32_t* __restrict__ dst, int n)
{
    for (int i = blockIdx.x * 256 + threadIdx.x; i < n; i += gridDim.x * 256) {
        float2 v = src[i];
        __half2 h = __floats2half2_rn(v.x, v.y);
        dst[i] = *(uint32_t*)&h;
    }
}

// W[K][N] f32 -> Wp[K/2][N], columns n < ncut scaled by factor
__global__ __launch_bounds__(256) void pack_w_kernel(
    const float* __restrict__ W, uint32_t* __restrict__ Wp, int K, int N,
    int ncut, float factor)
{
    const int total = (K / 2) * N;
    for (int i = blockIdx.x * 256 + threadIdx.x; i < total; i += gridDim.x * 256) {
        const int kk = i / N;
        const int n = i - kk * N;
        const float f = (n < ncut) ? factor : 1.f;
        __half2 h = __floats2half2_rn(W[(size_t)(2 * kk) * N + n] * f,
                                      W[(size_t)(2 * kk + 1) * N + n] * f);
        Wp[i] = *(uint32_t*)&h;
    }
}

__global__ __launch_bounds__(256) void scale_bias_kernel(
    const float* __restrict__ b, float* __restrict__ sb)
{
    int i = blockIdx.x * 256 + threadIdx.x;
    if (i < 3 * DIM) sb[i] = b[i] * (i < DIM ? QSCALE : 1.f);
}

// comb[w][h][i][j] = mask[w][i][j] + bias_table[rel_index[i*49+j]][h]
__global__ __launch_bounds__(256) void comb_kernel(
    const float* __restrict__ mask, const float* __restrict__ bias_table,
    const int* __restrict__ rel_index, float* __restrict__ comb)
{
    const int total = NWIN * HEADS * NTOK * NTOK;
    int idx = blockIdx.x * 256 + threadIdx.x;
    if (idx < total) {
        const int ij = idx % (NTOK * NTOK);
        const int wh = idx / (NTOK * NTOK);
        const int h = wh & (HEADS - 1);
        const int w = wh >> 3;
        comb[idx] = mask[w * NTOK * NTOK + ij] + bias_table[rel_index[ij] * HEADS + h];
    }
}

// ---------------------------------------------------------------------------
// FP16 mma.sync GEMM, 3-stage cp.async pipeline.
// C = A @ B + bias, A[M][K/2] packed, B[K/2][N] packed.
// BM=128, BN=128, BK=32, 128 threads (4 warps 2x2), warp tile 64x64.
// PACK_OUT: emit packed half2 (Cp) instead of f32 (Cf).
// ---------------------------------------------------------------------------
#define GEMM_STAGE_WORDS (128 * 20 + 16 * 136)
#define GEMM_STAGES 3
#define GEMM_SMEM_BYTES (GEMM_STAGES * GEMM_STAGE_WORDS * 4)

template<bool PACK_OUT>
__global__ __launch_bounds__(128) void gemm_fp16(
    const uint32_t* __restrict__ Ap, const uint32_t* __restrict__ Bp,
    const float* __restrict__ bias, float* __restrict__ Cf,
    uint32_t* __restrict__ Cp, int M, int N, int K)
{
    constexpr int ASTR = 20, BSTR = 136;
    const int K2 = K / 2;

    extern __shared__ uint32_t sm[];

    const int tid = threadIdx.x;
    const int wid = tid >> 5;
    const int lane = tid & 31;
    const int lr = lane >> 2;
    const int lc = lane & 3;
    const int wm = wid & 1;
    const int wn = wid >> 1;

    const int bm = blockIdx.y * 128;
    const int bn = blockIdx.x * 128;

    const uint32_t smem_base = (uint32_t)__cvta_generic_to_shared(sm);

    auto issue = [&](int k0, int s) {
        const int k20 = k0 >> 1;
        const uint32_t as_base = smem_base + (uint32_t)(s * GEMM_STAGE_WORDS) * 4;
        const uint32_t bs_base = as_base + 128 * ASTR * 4;
        #pragma unroll
        for (int i = 0; i < 4; i++) {
            const int idx = tid + 128 * i;
            const int r = idx >> 2, q = idx & 3;
            cp16(as_base + (r * ASTR + q * 4) * 4,
                 Ap + (size_t)(bm + r) * K2 + k20 + q * 4);
        }
        #pragma unroll
        for (int i = 0; i < 4; i++) {
            const int idx = tid + 128 * i;
            const int r = idx >> 5, c = idx & 31;
            cp16(bs_base + (r * BSTR + c * 4) * 4,
                 Bp + (size_t)(k20 + r) * N + bn + c * 4);
        }
        asm volatile("cp.async.commit_group;\n" ::);
    };

    float acc[4][8][4] = {};

    const int niter = K / 32;
    issue(0, 0);
    issue(32, 1);

    for (int it = 0; it < niter; it++) {
        if (it < niter - 1)
            asm volatile("cp.async.wait_group 1;\n" ::);
        else
            asm volatile("cp.async.wait_group 0;\n" ::);
        __syncthreads();

        const int s = it % GEMM_STAGES;
        const uint32_t* As = sm + s * GEMM_STAGE_WORDS;
        const uint32_t* Bs = As + 128 * ASTR;

        #pragma unroll
        for (int ks = 0; ks < 2; ks++) {
            const int k2b = ks * 8;
            uint32_t afr[4][4];
            #pragma unroll
            for (int mi = 0; mi < 4; mi++) {
                const int r = wm * 64 + mi * 16;
                afr[mi][0] = As[(r + lr) * ASTR + k2b + lc];
                afr[mi][1] = As[(r + 8 + lr) * ASTR + k2b + lc];
                afr[mi][2] = As[(r + lr) * ASTR + k2b + 4 + lc];
                afr[mi][3] = As[(r + 8 + lr) * ASTR + k2b + 4 + lc];
            }
            uint32_t bfr[8][2];
            #pragma unroll
            for (int ni = 0; ni < 8; ni++) {
                const int c = wn * 64 + ni * 8 + lr;
                bfr[ni][0] = Bs[(k2b + lc) * BSTR + c];
                bfr[ni][1] = Bs[(k2b + 4 + lc) * BSTR + c];
            }
            #pragma unroll
            for (int mi = 0; mi < 4; mi++)
                #pragma unroll
                for (int ni = 0; ni < 8; ni++)
                    mma_f16(acc[mi][ni], afr[mi], bfr[ni]);
        }

        if (it + 2 < niter) issue((it + 2) * 32, (it + 2) % GEMM_STAGES);
    }

    #pragma unroll
    for (int mi = 0; mi < 4; mi++) {
        #pragma unroll
        for (int ni = 0; ni < 8; ni++) {
            const int r0 = bm + wm * 64 + mi * 16 + lr;
            const int c0 = bn + wn * 64 + ni * 8 + lc * 2;
            float2 b01 = *(const float2*)(bias + c0);
            if (PACK_OUT) {
                __half2 h0 = __floats2half2_rn(acc[mi][ni][0] + b01.x,
                                               acc[mi][ni][1] + b01.y);
                __half2 h1 = __floats2half2_rn(acc[mi][ni][2] + b01.x,
                                               acc[mi][ni][3] + b01.y);
                Cp[(size_t)r0 * (N / 2) + (c0 >> 1)] = *(uint32_t*)&h0;
                Cp[(size_t)(r0 + 8) * (N / 2) + (c0 >> 1)] = *(uint32_t*)&h1;
            } else {
                float2 v0 = make_float2(acc[mi][ni][0] + b01.x, acc[mi][ni][1] + b01.y);
                float2 v1 = make_float2(acc[mi][ni][2] + b01.x, acc[mi][ni][3] + b01.y);
                *(float2*)(Cf + (size_t)r0 * N + c0) = v0;
                *(float2*)(Cf + (size_t)(r0 + 8) * N + c0) = v1;
            }
        }
    }
}

// ---------------------------------------------------------------------------
// FP16 attention: one block per (b, h), 4 warps, register softmax.
// Q/K smem = direct packed-word copies (q pre-scaled at pack time).
// smem: Qw 64x20 + Kw 56x20 + Vt 32x36 words = 14528 B.
// ---------------------------------------------------------------------------
__global__ __launch_bounds__(128) void attn_fp16_kernel(
    const uint32_t* __restrict__ qkvp,   // [M][384] packed half2
    const float* __restrict__ comb,      // [64][8][49][49]
    uint32_t* __restrict__ outp)         // [M][128] packed half2
{
    __shared__ __align__(16) uint32_t sw[3632];
    uint32_t* Qw = sw;            // 64 x 20 (rows >=49 garbage, rows discarded)
    uint32_t* Kw = sw + 1280;     // 56 x 20 (rows >=49 garbage, masked in softmax)
    uint32_t* Vt = sw + 2480;     // 32 x 36 words = [d][j-pairs], j pads zeroed

    const int b = blockIdx.x;
    const int h = blockIdx.y;
    const int tid = threadIdx.x;
    const int wid = tid >> 5;
    const int lane = tid & 31;
    const int lr = lane >> 2;
    const int lc = lane & 3;

    const uint32_t* base = qkvp + (size_t)b * NTOK * 384 + h * 16;

    // zero V-transpose pad halves j = 49..63
    {
        __half* vtH = (__half*)Vt;
        for (int e = tid; e < HD * 15; e += 128) {
            const int d = e / 15;
            const int j = NTOK + (e % 15);
            vtH[d * 72 + j] = __float2half(0.f);
        }
    }
    // load Q/K words directly; V transposed via half stores
    {
        __half* vtH = (__half*)Vt;
        for (int w = tid; w < NTOK * 16; w += 128) {
            const int j = w >> 4;
            const int dd = w & 15;
            const uint32_t* row = base + (size_t)j * 384;
            Qw[j * 20 + dd] = row[dd];
            Kw[j * 20 + dd] = row[128 + dd];
            uint32_t v = row[256 + dd];
            __half2 hv = *(__half2*)&v;
            vtH[(2 * dd) * 72 + j] = __low2half(hv);
            vtH[(2 * dd + 1) * 72 + j] = __high2half(hv);
        }
    }
    __syncthreads();

    const int mr = wid * 16;

    // ---- S = Qs @ K^T : fp16, 2 k16-steps x 7 n-tiles = 14 mma ----
    float sacc[7][4] = {};
    #pragma unroll
    for (int kt = 0; kt < 2; kt++) {
        const int kw = kt * 8;
        uint32_t a[4];
        a[0] = Qw[(mr + lr) * 20 + kw + lc];
        a[1] = Qw[(mr + 8 + lr) * 20 + kw + lc];
        a[2] = Qw[(mr + lr) * 20 + kw + 4 + lc];
        a[3] = Qw[(mr + 8 + lr) * 20 + kw + 4 + lc];
        #pragma unroll
        for (int nt = 0; nt < 7; nt++) {
            const int n0 = nt * 8;
            uint32_t bfr[2];
            bfr[0] = Kw[(n0 + lr) * 20 + kw + lc];
            bfr[1] = Kw[(n0 + lr) * 20 + kw + 4 + lc];
            mma_f16(sacc[nt], a, bfr);
        }
    }

    // ---- register softmax: add comb, quad shuffles, normalize ----
    {
        const float* cb = comb + ((size_t)((b & (NWIN - 1)) * HEADS + h)) * (NTOK * NTOK);
        const int rA = mr + lr;
        const int rB = mr + 8 + lr;
        const bool okA = rA < NTOK;
        const bool okB = rB < NTOK;
        float mA = -CUDART_INF_F, mB = -CUDART_INF_F;

        #pragma unroll
        for (int nt = 0; nt < 7; nt++) {
            const int c0 = nt * 8 + 2 * lc;
            const bool ok0 = c0 < NTOK;
            const bool ok1 = (c0 + 1) < NTOK;
            float v0A = (okA && ok0) ? sacc[nt][0] + __ldg(cb + rA * NTOK + c0)     : -CUDART_INF_F;
            float v1A = (okA && ok1) ? sacc[nt][1] + __ldg(cb + rA * NTOK + c0 + 1) : -CUDART_INF_F;
            float v0B = (okB && ok0) ? sacc[nt][2] + __ldg(cb + rB * NTOK + c0)     : -CUDART_INF_F;
            float v1B = (okB && ok1) ? sacc[nt][3] + __ldg(cb + rB * NTOK + c0 + 1) : -CUDART_INF_F;
            sacc[nt][0] = v0A; sacc[nt][1] = v1A;
            sacc[nt][2] = v0B; sacc[nt][3] = v1B;
            mA = fmaxf(mA, fmaxf(v0A, v1A));
            mB = fmaxf(mB, fmaxf(v0B, v1B));
        }
        mA = fmaxf(mA, __shfl_xor_sync(0xffffffffu, mA, 1));
        mA = fmaxf(mA, __shfl_xor_sync(0xffffffffu, mA, 2));
        mB = fmaxf(mB, __shfl_xor_sync(0xffffffffu, mB, 1));
        mB = fmaxf(mB, __shfl_xor_sync(0xffffffffu, mB, 2));

        float sA = 0.f, sB = 0.f;
        #pragma unroll
        for (int nt = 0; nt < 7; nt++) {
            float e0A = __expf(sacc[nt][0] - mA);
            float e1A = __expf(sacc[nt][1] - mA);
            float e0B = __expf(sacc[nt][2] - mB);
            float e1B = __expf(sacc[nt][3] - mB);
            sacc[nt][0] = e0A; sacc[nt][1] = e1A;
            sacc[nt][2] = e0B; sacc[nt][3] = e1B;
            sA += e0A + e1A;
            sB += e0B + e1B;
        }
        sA += __shfl_xor_sync(0xffffffffu, sA, 1);
        sA += __shfl_xor_sync(0xffffffffu, sA, 2);
        sB += __shfl_xor_sync(0xffffffffu, sB, 1);
        sB += __shfl_xor_sync(0xffffffffu, sB, 2);
        const float invA = 1.f / sA;
        const float invB = 1.f / sB;
        #pragma unroll
        for (int nt = 0; nt < 7; nt++) {
            sacc[nt][0] *= invA; sacc[nt][1] *= invA;
            sacc[nt][2] *= invB; sacc[nt][3] *= invB;
        }
    }

    // ---- O = P @ V : fp16, 4 k16-steps x 4 n-tiles = 16 mma ----
    {
        float oacc[4][4] = {};
        #pragma unroll
        for (int kt = 0; kt < 4; kt++) {
            const int t0 = 2 * kt;
            const int t1 = 2 * kt + 1;
            uint32_t a[4];
            __half2 p0 = __floats2half2_rn(sacc[t0][0], sacc[t0][1]);
            __half2 p1 = __floats2half2_rn(sacc[t0][2], sacc[t0][3]);
            a[0] = *(uint32_t*)&p0;
            a[1] = *(uint32_t*)&p1;
            if (t1 < 7) {
                __half2 p2 = __floats2half2_rn(sacc[t1][0], sacc[t1][1]);
                __half2 p3 = __floats2half2_rn(sacc[t1][2], sacc[t1][3]);
                a[2] = *(uint32_t*)&p2;
                a[3] = *(uint32_t*)&p3;
            } else {
                a[2] = a[3] = 0u;
            }
            #pragma unroll
            for (int nt = 0; nt < 4; nt++) {
                const int n0 = nt * 8;
                uint32_t bfr[2];
                bfr[0] = Vt[(n0 + lr) * 36 + kt * 8 + lc];
                bfr[1] = Vt[(n0 + lr) * 36 + kt * 8 + 4 + lc];
                mma_f16(oacc[nt], a, bfr);
            }
        }

        const int r0 = mr + lr;
        const int r1 = mr + 8 + lr;
        #pragma unroll
        for (int nt = 0; nt < 4; nt++) {
            const int w0 = (h * HD + nt * 8 + lc * 2) >> 1;
            if (r0 < NTOK) {
                __half2 hv = __floats2half2_rn(oacc[nt][0], oacc[nt][1]);
                outp[((size_t)b * NTOK + r0) * (DIM / 2) + w0] = *(uint32_t*)&hv;
            }
            if (r1 < NTOK) {
                __half2 hv = __floats2half2_rn(oacc[nt][2], oacc[nt][3]);
                outp[((size_t)b * NTOK + r1) * (DIM / 2) + w0] = *(uint32_t*)&hv;
            }
        }
    }
}

// ---------------------------------------------------------------------------
extern "C" void kernel_launch(void* const* d_in, const int* in_sizes, int n_in,
                              void* d_out, int out_size)
{
    const float* x          = (const float*)d_in[0];
    const float* mask       = (const float*)d_in[1];
    const float* qkv_w      = (const float*)d_in[2];
    const float* qkv_b      = (const float*)d_in[3];
    const float* proj_w     = (const float*)d_in[4];
    const float* proj_b     = (const float*)d_in[5];
    const float* bias_table = (const float*)d_in[6];
    const int*   rel_index  = (const int*)d_in[7];
    float* out = (float*)d_out;

    uint32_t *xp_buf, *qkvp_buf, *aop_buf, *wqp_buf, *wpp_buf;
    float *qbs_buf, *comb_buf;
    cudaGetSymbolAddress((void**)&xp_buf, g_xp);
    cudaGetSymbolAddress((void**)&qkvp_buf, g_qkvp);
    cudaGetSymbolAddress((void**)&aop_buf, g_aop);
    cudaGetSymbolAddress((void**)&wqp_buf, g_wqp);
    cudaGetSymbolAddress((void**)&wpp_buf, g_wpp);
    cudaGetSymbolAddress((void**)&qbs_buf, g_qbs);
    cudaGetSymbolAddress((void**)&comb_buf, g_comb);

    static bool attr_set = false;
    if (!attr_set) {
        cudaFuncSetAttribute(gemm_fp16<true>,
                             cudaFuncAttributeMaxDynamicSharedMemorySize,
                             GEMM_SMEM_BYTES);
        cudaFuncSetAttribute(gemm_fp16<false>,
                             cudaFuncAttributeMaxDynamicSharedMemorySize,
                             GEMM_SMEM_BYTES);
        attr_set = true;
    }

    const int M = BATCH * NTOK;   // 100352 = 128 * 784

    // 0) prep
    pack_fp16_kernel<<<2048, 256>>>((const float2*)x, xp_buf, M * DIM / 2);
    pack_w_kernel<<<384, 256>>>(qkv_w, wqp_buf, DIM, 3 * DIM, DIM, QSCALE);
    pack_w_kernel<<<128, 256>>>(proj_w, wpp_buf, DIM, DIM, 0, 1.f);
    scale_bias_kernel<<<3, 256>>>(qkv_b, qbs_buf);
    {
        const int total = NWIN * HEADS * NTOK * NTOK;
        comb_kernel<<<(total + 255) / 256, 256>>>(mask, bias_table, rel_index, comb_buf);
    }
    // 1) QKV GEMM (fp16, packed output, q pre-scaled)
    {
        dim3 grid(3 * DIM / 128, M / 128);
        gemm_fp16<true><<<grid, 128, GEMM_SMEM_BYTES>>>(
            xp_buf, wqp_buf, qbs_buf, nullptr, qkvp_buf, M, 3 * DIM, DIM);
    }
    // 2) fp16 attention -> packed half2
    {
        dim3 grid(BATCH, HEADS);
        attn_fp16_kernel<<<grid, 128>>>(qkvp_buf, comb_buf, aop_buf);
    }
    // 3) Proj GEMM (fp16, f32 output)
    {
        dim3 grid(DIM / 128, M / 128);
        gemm_fp16<false><<<grid, 128, GEMM_SMEM_BYTES>>>(
            aop_buf, wpp_buf, proj_b, out, nullptr, M, DIM, DIM);
    }
}